// round 5
// baseline (speedup 1.0000x reference)
#include <cuda_runtime.h>
#include <cuda_bf16.h>
#include <cstdint>

// ---------------- problem shape ----------------
#define TOK   32768
#define HDIM  4096
#define NE    64
#define BM    128            // tokens per CTA
#define BK    64             // k per chunk
#define NCH   64             // HDIM / BK
#define NT    256            // threads (8 warps, 1 m-tile each)
#define TAU   1e-4f

// smem per buffer (SW128-swizzled, 128B rows):
//  XH[128][128B]  @ 0       (16384 B)
//  XL[128][128B]  @ 16384
//  WH[64][128B]   @ 32768   (8192 B)
//  WL[64][128B]   @ 40960
#define XH_OFF 0
#define XL_OFF 16384
#define WH_OFF 32768
#define WL_OFF 40960
#define BUFB   49152
#define SMEMB  (2 * BUFB)    // 98304 bytes

// ---------------- device globals ----------------
// g_w: [chunk 64][plane 2][expert 64][64 bf16 = 128B]  (linear, 1 MB)
__device__ uint32_t g_w[NCH * 2 * 2048];
__device__ int g_flag_count;
__device__ int g_flag_list[TOK];

// ---------------- helpers ----------------
__device__ __forceinline__ uint32_t s2u(const void* p) {
    uint32_t a;
    asm("{ .reg .u64 t; cvta.to.shared.u64 t, %1; cvt.u32.u64 %0, t; }" : "=r"(a) : "l"(p));
    return a;
}
__device__ __forceinline__ uint32_t sw128(uint32_t o) { return o ^ ((o >> 3) & 0x70); }

__device__ __forceinline__ uint32_t cvt2(float f1, float f0) {
    uint32_t d;
    asm("cvt.rn.bf16x2.f32 %0, %1, %2;" : "=r"(d) : "f"(f1), "f"(f0));
    return d;
}
__device__ __forceinline__ void splitpair(float f0, float f1, uint32_t& h, uint32_t& l) {
    h = cvt2(f1, f0);
    float h0 = __uint_as_float(h << 16);
    float h1 = __uint_as_float(h & 0xFFFF0000u);
    l = cvt2(f1 - h1, f0 - h0);
}
__device__ __forceinline__ void ldsm4(uint32_t* r, uint32_t addr) {
    asm volatile("ldmatrix.sync.aligned.m8n8.x4.shared.b16 {%0,%1,%2,%3}, [%4];"
                 : "=r"(r[0]), "=r"(r[1]), "=r"(r[2]), "=r"(r[3]) : "r"(addr));
}
__device__ __forceinline__ void mma16816(float* c, const uint32_t* a,
                                         uint32_t b0, uint32_t b1) {
    asm("mma.sync.aligned.m16n8k16.row.col.f32.bf16.bf16.f32 "
        "{%0,%1,%2,%3}, {%4,%5,%6,%7}, {%8,%9}, {%0,%1,%2,%3};"
        : "+f"(c[0]), "+f"(c[1]), "+f"(c[2]), "+f"(c[3])
        : "r"(a[0]), "r"(a[1]), "r"(a[2]), "r"(a[3]), "r"(b0), "r"(b1));
}
__device__ __forceinline__ void cpasync16(uint32_t dst, const void* src) {
    asm volatile("cp.async.ca.shared.global [%0], [%1], 16;" :: "r"(dst), "l"(src));
}
#define CP_COMMIT() asm volatile("cp.async.commit_group;" ::: "memory")
#define CP_WAIT0()  asm volatile("cp.async.wait_group 0;" ::: "memory")

// ---------------- prep: W fp32 -> (h,l) bf16-pair planes, linear layout ----------------
__global__ void prep_w(const float* __restrict__ W) {
    int id = blockIdx.x * 256 + threadIdx.x;
    if (id == 0) g_flag_count = 0;
    if (id >= NCH * NE) return;
    int c = id >> 6, e = id & 63;
    const float* src = W + (size_t)e * HDIM + c * BK;
    uint32_t* dh = g_w + (c * 2 + 0) * 2048 + e * 32;
    uint32_t* dl = g_w + (c * 2 + 1) * 2048 + e * 32;
#pragma unroll
    for (int kp = 0; kp < 32; ++kp) {
        uint32_t h, l;
        splitpair(src[2 * kp], src[2 * kp + 1], h, l);
        dh[kp] = h;
        dl[kp] = l;
    }
}

// ---------------- main: bf16x2 HMMA GEMM + fused softmax/top2 ----------------
__global__ void __launch_bounds__(NT, 2)
moe_gate_mma(const float* __restrict__ X, float* __restrict__ out) {
    extern __shared__ char smem_raw[];
    const uint32_t sbase = s2u(smem_raw);

    const int tid  = threadIdx.x;
    const int lane = tid & 31, wid = tid >> 5;       // 8 warps
    const int lrow = lane & 15, lkh = lane >> 4;
    const int tok0 = blockIdx.x * BM;
    const float* Xg = X + (size_t)tok0 * HDIM;

    // ldmatrix lane base addresses (buffer offset added per chunk; ks applied via XOR)
    const int arow = wid * 16 + lrow;
    const uint32_t aSw = (uint32_t)(arow * 128) + (((uint32_t)(lkh * 16)) ^ ((uint32_t)(arow & 7) << 4));
    const uint32_t aH = sbase + XH_OFF + aSw;
    const uint32_t aL = sbase + XL_OFF + aSw;
    uint32_t bH[4], bL[4];
#pragma unroll
    for (int np = 0; np < 4; ++np) {
        int brow = np * 16 + lrow;
        uint32_t bSw = (uint32_t)(brow * 128) + (((uint32_t)(lkh * 16)) ^ ((uint32_t)(brow & 7) << 4));
        bH[np] = sbase + WH_OFF + bSw;
        bL[np] = sbase + WL_OFF + bSw;
    }

    float acc[8][4];
#pragma unroll
    for (int nt = 0; nt < 8; ++nt)
#pragma unroll
        for (int q = 0; q < 4; ++q) acc[nt][q] = 0.0f;

    float4 xa[8];

    // ---- helper lambdas as macros: LDG X chunk, cp.async W chunk, convert+STS ----
#define LDG_X(cc)                                                               \
    {                                                                           \
        const int kb = (cc) * BK;                                               \
        _Pragma("unroll")                                                       \
        for (int it = 0; it < 8; ++it) {                                        \
            int f = it * NT + tid;                                              \
            int row = f >> 4, k4 = f & 15;                                      \
            xa[it] = *(const float4*)(Xg + (size_t)row * HDIM + kb + k4 * 4);   \
        }                                                                       \
    }

#define CP_W(cc, bufo)                                                          \
    {                                                                           \
        const char* wsrc = (const char*)g_w + (size_t)(cc) * 16384;             \
        _Pragma("unroll")                                                       \
        for (int q = 0; q < 4; ++q) {                                           \
            int idx = q * NT + tid;            /* 0..1023 */                    \
            int pl = idx >> 9, rest = idx & 511;                                \
            int row = rest >> 3, blk = rest & 7;                                \
            uint32_t dst = sbase + (bufo) + WH_OFF + pl * 8192 +                \
                           sw128((uint32_t)(row * 128 + blk * 16));             \
            cpasync16(dst, wsrc + pl * 8192 + row * 128 + blk * 16);            \
        }                                                                       \
        CP_COMMIT();                                                            \
    }

#define CVT_X(bufo)                                                             \
    {                                                                           \
        _Pragma("unroll")                                                       \
        for (int it = 0; it < 8; ++it) {                                        \
            int f = it * NT + tid;                                              \
            int row = f >> 4, k4 = f & 15;                                      \
            uint32_t h0, l0, h1, l1;                                            \
            splitpair(xa[it].x, xa[it].y, h0, l0);                              \
            splitpair(xa[it].z, xa[it].w, h1, l1);                              \
            uint32_t sw = sw128((uint32_t)(row * 128 + k4 * 8));                \
            *(uint2*)(smem_raw + (bufo) + XH_OFF + sw) = make_uint2(h0, h1);    \
            *(uint2*)(smem_raw + (bufo) + XL_OFF + sw) = make_uint2(l0, l1);    \
        }                                                                       \
    }

    // ---- stage chunk 0 ----
    LDG_X(0);
    CP_W(0, 0);
    CVT_X(0);
    CP_WAIT0();
    __syncthreads();

    // ---- main loop over 64 chunks ----
    for (int c = 0; c < NCH; ++c) {
        const uint32_t bufR = (uint32_t)(c & 1) * BUFB;
        const uint32_t bufW = (uint32_t)((c + 1) & 1) * BUFB;
        const bool more = (c + 1 < NCH);

        if (more) {
            LDG_X(c + 1);
            CP_W(c + 1, bufW);
        }

        // mma on current buffer: 4 ksteps x 4 np-tiles x 2 sub x 3 passes = 96
#pragma unroll
        for (int ks = 0; ks < 4; ++ks) {
            const uint32_t kx = (uint32_t)(ks * 32);
            uint32_t Ah[4], Al[4];
            ldsm4(Ah, (aH + bufR) ^ kx);
            ldsm4(Al, (aL + bufR) ^ kx);
#pragma unroll
            for (int np = 0; np < 4; ++np) {
                uint32_t Bh[4], Bl[4];
                ldsm4(Bh, (bH[np] + bufR) ^ kx);
                ldsm4(Bl, (bL[np] + bufR) ^ kx);
#pragma unroll
                for (int sub = 0; sub < 2; ++sub) {
                    float* cc = acc[np * 2 + sub];
                    mma16816(cc, Ah, Bh[sub], Bh[2 + sub]);   // h*h
                    mma16816(cc, Ah, Bl[sub], Bl[2 + sub]);   // h*l
                    mma16816(cc, Al, Bh[sub], Bh[2 + sub]);   // l*h
                }
            }
        }

        if (more) {
            CVT_X(bufW);
            CP_WAIT0();
        }
        __syncthreads();
    }

    // ---- scatter logits into smem overlay lg[128][65] ----
    float* lg = (float*)smem_raw;
    const int g = lane >> 2, tig = lane & 3;
#pragma unroll
    for (int nt = 0; nt < 8; ++nt) {
        int r0 = wid * 16 + g;
        int e0 = nt * 8 + tig * 2;
        lg[r0 * 65 + e0]           = acc[nt][0];
        lg[r0 * 65 + e0 + 1]       = acc[nt][1];
        lg[(r0 + 8) * 65 + e0]     = acc[nt][2];
        lg[(r0 + 8) * 65 + e0 + 1] = acc[nt][3];
    }
    __syncthreads();

    // ---- per-token softmax + top-3 + near-tie flag (threads 0..127) ----
    if (tid < BM) {
        const int t = tid;
        const float* row = lg + t * 65;
        float mx = row[0];
#pragma unroll 8
        for (int e = 1; e < NE; ++e) mx = fmaxf(mx, row[e]);
        float sum = 0.0f;
        float s1 = -3.4e38f, s2 = -3.4e38f, s3 = -3.4e38f;
        int i1 = 0, i2 = 0;
#pragma unroll 8
        for (int e = 0; e < NE; ++e) {
            float l = row[e];
            sum += expf(l - mx);
            if (l > s1)      { s3 = s2; s2 = s1; i2 = i1; s1 = l; i1 = e; }
            else if (l > s2) { s3 = s2; s2 = l; i2 = e; }
            else if (l > s3) { s3 = l; }
        }
        float inv = 1.0f / sum;
        int gt = tok0 + t;
        out[2 * gt]               = (float)i1;
        out[2 * gt + 1]           = (float)i2;
        out[2 * TOK + 2 * gt]     = expf(s1 - mx) * inv;
        out[2 * TOK + 2 * gt + 1] = expf(s2 - mx) * inv;
        if ((s1 - s2 < TAU) || (s2 - s3 < TAU)) {
            int sl = atomicAdd(&g_flag_count, 1);
            if (sl < TOK) g_flag_list[sl] = gt;
        }
    }
}

// ---------------- cleanup: fp64 recompute of near-tie tokens ----------------
__global__ void cleanup_kernel(const float* __restrict__ X, const float* __restrict__ W,
                               float* __restrict__ out) {
    __shared__ double sred[128];
    __shared__ double lgs[64];
    int nf = g_flag_count;
    if (nf > TOK) nf = TOK;
    for (int i = blockIdx.x; i < nf; i += gridDim.x) {
        int t = g_flag_list[i];
        int e  = threadIdx.x & 63;
        int kh = threadIdx.x >> 6;
        const float* xr = X + (size_t)t * HDIM + kh * 2048;
        const float* wr = W + (size_t)e * HDIM + kh * 2048;
        double a = 0.0;
        for (int k = 0; k < 2048; ++k)
            a += (double)xr[k] * (double)wr[k];
        sred[threadIdx.x] = a;
        __syncthreads();
        if (threadIdx.x < 64) lgs[threadIdx.x] = sred[threadIdx.x] + sred[threadIdx.x + 64];
        __syncthreads();
        if (threadIdx.x == 0) {
            double mx = lgs[0];
            for (int q = 1; q < NE; ++q) if (lgs[q] > mx) mx = lgs[q];
            double sum = 0.0;
            double s1 = -1e300, s2 = -1e300;
            int i1 = 0, i2 = 0;
            for (int q = 0; q < NE; ++q) {
                double l = lgs[q];
                sum += exp(l - mx);
                if (l > s1)      { s2 = s1; i2 = i1; s1 = l; i1 = q; }
                else if (l > s2) { s2 = l; i2 = q; }
            }
            double inv = 1.0 / sum;
            out[2 * t]               = (float)i1;
            out[2 * t + 1]           = (float)i2;
            out[2 * TOK + 2 * t]     = (float)(exp(s1 - mx) * inv);
            out[2 * TOK + 2 * t + 1] = (float)(exp(s2 - mx) * inv);
        }
        __syncthreads();
    }
}

// ---------------- launch ----------------
extern "C" void kernel_launch(void* const* d_in, const int* in_sizes, int n_in,
                              void* d_out, int out_size) {
    const float* X = (const float*)d_in[0];
    const float* W = (const float*)d_in[1];
    float* out = (float*)d_out;

    static bool once = []() {
        cudaFuncSetAttribute(moe_gate_mma, cudaFuncAttributeMaxDynamicSharedMemorySize,
                             SMEMB);
        return true;
    }();
    (void)once;

    prep_w<<<(NCH * NE + 255) / 256, 256>>>(W);
    moe_gate_mma<<<TOK / BM, NT, SMEMB>>>(X, out);
    cleanup_kernel<<<128, 128>>>(X, W, out);
}